// round 3
// baseline (speedup 1.0000x reference)
#include <cuda_runtime.h>
#include <cuda_bf16.h>
#include <cstdint>
#include <cstddef>

// Problem constants
#define NUM_STATE 2048
#define BATCH     4096

// ---------------------------------------------------------------------------
// Scratch (device globals; no cudaMalloc allowed)
// ---------------------------------------------------------------------------
__device__ __align__(16) __nv_bfloat16 g_alphaB[(size_t)BATCH * NUM_STATE];     // 16 MB
__device__ __align__(16) __nv_bfloat16 g_matT[(size_t)NUM_STATE * NUM_STATE];   // 8 MB, matT[t][s] = mat[s][t]
__device__ float g_rmax[NUM_STATE];
__device__ float g_rinv[NUM_STATE];

// ---------------------------------------------------------------------------
// Helpers
// ---------------------------------------------------------------------------
__device__ __forceinline__ uint32_t smem_u32(const void* p) {
    uint32_t a;
    asm("{ .reg .u64 t; cvta.to.shared.u64 t, %1; cvt.u32.u64 %0, t; }" : "=r"(a) : "l"(p));
    return a;
}

#define SWZ128(off) ((off) ^ (((off) >> 3) & 0x70))

__device__ __forceinline__ void cp_async16(uint32_t s, const void* g) {
    asm volatile("cp.async.cg.shared.global [%0], [%1], 16;" :: "r"(s), "l"(g) : "memory");
}
#define CP_COMMIT() asm volatile("cp.async.commit_group;" ::: "memory")
template <int N>
__device__ __forceinline__ void cp_wait() {
    asm volatile("cp.async.wait_group %0;" :: "n"(N) : "memory");
}

__device__ __forceinline__ void ldsm4(uint32_t* r, uint32_t addr) {
    asm volatile("ldmatrix.sync.aligned.m8n8.x4.shared.b16 {%0,%1,%2,%3}, [%4];"
                 : "=r"(r[0]), "=r"(r[1]), "=r"(r[2]), "=r"(r[3]) : "r"(addr));
}

__device__ __forceinline__ void mma_bf16(float* c, const uint32_t* a,
                                         uint32_t b0, uint32_t b1) {
    asm volatile(
        "mma.sync.aligned.m16n8k16.row.col.f32.bf16.bf16.f32 "
        "{%0,%1,%2,%3}, {%4,%5,%6,%7}, {%8,%9}, {%0,%1,%2,%3};"
        : "+f"(c[0]), "+f"(c[1]), "+f"(c[2]), "+f"(c[3])
        : "r"(a[0]), "r"(a[1]), "r"(a[2]), "r"(a[3]), "r"(b0), "r"(b1));
}

// ---------------------------------------------------------------------------
// Kernel 1: per-row softmax stats (max, 1/sum) over 2047 columns
// ---------------------------------------------------------------------------
__global__ void row_stats_kernel(const float* __restrict__ utm) {
    const int s = blockIdx.x;
    const float* row = utm + (size_t)s * (NUM_STATE - 1);
    const int tid = threadIdx.x;

    __shared__ float red[8];
    __shared__ float s_mx;

    float mx = -3.4e38f;
    for (int j = tid; j < NUM_STATE - 1; j += 256) mx = fmaxf(mx, row[j]);
    #pragma unroll
    for (int o = 16; o; o >>= 1) mx = fmaxf(mx, __shfl_xor_sync(0xffffffffu, mx, o));
    if ((tid & 31) == 0) red[tid >> 5] = mx;
    __syncthreads();
    if (tid == 0) {
        float m = red[0];
        #pragma unroll
        for (int i = 1; i < 8; i++) m = fmaxf(m, red[i]);
        s_mx = m;
    }
    __syncthreads();
    const float m = s_mx;

    float sm = 0.f;
    for (int j = tid; j < NUM_STATE - 1; j += 256) sm += __expf(row[j] - m);
    #pragma unroll
    for (int o = 16; o; o >>= 1) sm += __shfl_xor_sync(0xffffffffu, sm, o);
    if ((tid & 31) == 0) red[tid >> 5] = sm;
    __syncthreads();
    if (tid == 0) {
        float t = 0.f;
        #pragma unroll
        for (int i = 0; i < 8; i++) t += red[i];
        g_rmax[s] = m;
        g_rinv[s] = 1.0f / t;
    }
}

// ---------------------------------------------------------------------------
// Kernel 2: build matT[t][s] = mat[s][t] in bf16 (transposed so GEMM B operand
// is [N][K] row-major). mat[s][t] = (t==s) ? 0 : exp(u[s][t-(t>s)] - max[s]) * inv[s]
// ---------------------------------------------------------------------------
__global__ void build_matT_kernel(const float* __restrict__ utm) {
    const int s0 = blockIdx.x * 32;
    const int t0 = blockIdx.y * 32;
    const int tx = threadIdx.x;     // -> s
    const int ty = threadIdx.y;     // -> t (x4)
    const int tl = ty * 32 + tx;

    __shared__ float su[32][34];    // su[sy][cx] = u[s0+sy][t0-1+cx], cx in [0,33)

    for (int i = tl; i < 32 * 33; i += 256) {
        const int sy = i / 33;
        const int cx = i % 33;
        const int c = t0 - 1 + cx;
        su[sy][cx] = (c >= 0 && c < NUM_STATE - 1)
                       ? utm[(size_t)(s0 + sy) * (NUM_STATE - 1) + c] : 0.f;
    }
    __syncthreads();

    const int s = s0 + tx;
    const float mx = g_rmax[s];
    const float inv = g_rinv[s];

    #pragma unroll
    for (int k = 0; k < 4; k++) {
        const int yy = ty + 8 * k;
        const int t = t0 + yy;
        float v;
        if (t == s) {
            v = 0.f;
        } else {
            const int cx = yy + 1 - (t > s);   // = (t - (t>s)) - (t0-1)
            v = __expf(su[tx][cx] - mx) * inv;
        }
        g_matT[(size_t)t * NUM_STATE + s] = __float2bfloat16(v);
    }
}

// ---------------------------------------------------------------------------
// Kernel 3: alpha fp32 -> bf16
// ---------------------------------------------------------------------------
__global__ void cvt_alpha_kernel(const float* __restrict__ a) {
    const size_t i = ((size_t)blockIdx.x * blockDim.x + threadIdx.x) * 4;
    const float4 v = *reinterpret_cast<const float4*>(a + i);
    __nv_bfloat162 p0 = __floats2bfloat162_rn(v.x, v.y);
    __nv_bfloat162 p1 = __floats2bfloat162_rn(v.z, v.w);
    uint2 w;
    w.x = *reinterpret_cast<uint32_t*>(&p0);
    w.y = *reinterpret_cast<uint32_t*>(&p1);
    *reinterpret_cast<uint2*>(&g_alphaB[i]) = w;
}

// ---------------------------------------------------------------------------
// Kernel 4: mma.sync bf16 GEMM, C[4096,2048] = A[4096,2048] @ matT^T
//   A = g_alphaB  [M=4096][K=2048] row-major bf16
//   B = g_matT    [N=2048][K=2048] row-major bf16  (== col-major B for .row.col)
// CTA tile 128x128x64, 4-stage cp.async pipeline, 8 warps (4x2), warp 32x64.
// ---------------------------------------------------------------------------
static constexpr int BM = 128, BN = 128, BK = 64, STAGES = 4;
static constexpr int KITERS = NUM_STATE / BK;                       // 32
static constexpr int TILE_BYTES = BM * BK * 2;                      // 16384 (128B/row)
static constexpr int STAGE_BYTES = 2 * TILE_BYTES;                  // 32768
static constexpr int DYN_SMEM = STAGES * STAGE_BYTES + 1024;        // 132096

__global__ __launch_bounds__(256, 1) void gemm_kernel(float* __restrict__ out) {
    extern __shared__ char dsm[];
    const uint32_t dyn_base = (smem_u32(dsm) + 1023u) & ~1023u;

    const int tid = threadIdx.x;
    const int wid = tid >> 5;
    const int lane = tid & 31;

    const int tile = blockIdx.x;
    const int n0 = (tile & 15) * BN;
    const int m0 = (tile >> 4) * BM;

    const int warp_m = wid & 3;     // 4 slices of 32 rows
    const int warp_n = wid >> 2;    // 2 slices of 64 cols

    // ldmatrix x4 per-lane addressing: lanes 0-15 -> rows 0-15 of 16-row tile,
    // lanes 16-31 -> same rows, +16B (next 8 k-elems).
    const int lrow = lane & 15;
    const int lcol16 = (lane >> 4) & 1;

    auto load_stage = [&](int kit) {
        const int buf = kit & (STAGES - 1);
        const uint32_t sA = dyn_base + buf * STAGE_BYTES;
        const uint32_t sB = sA + TILE_BYTES;
        const int k0 = kit * BK;
        #pragma unroll
        for (int r = 0; r < 4; r++) {
            const int idx = tid + r * 256;       // 0..1023
            const int row = idx >> 3;
            const int c16 = idx & 7;
            const uint32_t soff = SWZ128((uint32_t)(row * 128 + c16 * 16));
            cp_async16(sA + soff, &g_alphaB[(size_t)(m0 + row) * NUM_STATE + k0 + c16 * 8]);
            cp_async16(sB + soff, &g_matT [(size_t)(n0 + row) * NUM_STATE + k0 + c16 * 8]);
        }
        CP_COMMIT();
    };

    float c[2][8][4];
    #pragma unroll
    for (int i = 0; i < 2; i++)
        #pragma unroll
        for (int j = 0; j < 8; j++)
            #pragma unroll
            for (int k = 0; k < 4; k++) c[i][j][k] = 0.f;

    // Prologue
    #pragma unroll
    for (int i = 0; i < STAGES - 1; i++) load_stage(i);

    for (int kit = 0; kit < KITERS; kit++) {
        const int buf = kit & (STAGES - 1);
        cp_wait<STAGES - 2>();
        __syncthreads();

        // Issue next stage load first so cp.async overlaps compute
        if (kit + STAGES - 1 < KITERS) load_stage(kit + STAGES - 1);

        const uint32_t sA = dyn_base + buf * STAGE_BYTES;
        const uint32_t sB = sA + TILE_BYTES;

        #pragma unroll
        for (int ks = 0; ks < BK / 16; ks++) {
            uint32_t a[2][4], b[4][4];
            #pragma unroll
            for (int mi = 0; mi < 2; mi++) {
                const uint32_t off = (uint32_t)((warp_m * 32 + mi * 16 + lrow) * 128
                                                + ks * 32 + lcol16 * 16);
                ldsm4(a[mi], sA + SWZ128(off));
            }
            #pragma unroll
            for (int nj = 0; nj < 4; nj++) {
                const uint32_t off = (uint32_t)((warp_n * 64 + nj * 16 + lrow) * 128
                                                + ks * 32 + lcol16 * 16);
                ldsm4(b[nj], sB + SWZ128(off));
            }
            // ldmatrix x4 register layout (with the addressing above):
            //   b[nj][0] = (n 0-7 , k 0-7)   b[nj][1] = (n 8-15, k 0-7)
            //   b[nj][2] = (n 0-7 , k 8-15)  b[nj][3] = (n 8-15, k 8-15)
            // mma B operand (k16n8) needs {k0-7, k8-15} of the SAME n-block:
            //   first  mma (n 0-7 ):  b0 = b[nj][0], b1 = b[nj][2]
            //   second mma (n 8-15):  b0 = b[nj][1], b1 = b[nj][3]
            #pragma unroll
            for (int mi = 0; mi < 2; mi++)
                #pragma unroll
                for (int nj = 0; nj < 4; nj++) {
                    mma_bf16(c[mi][nj * 2 + 0], a[mi], b[nj][0], b[nj][2]);
                    mma_bf16(c[mi][nj * 2 + 1], a[mi], b[nj][1], b[nj][3]);
                }
        }
    }

    // Epilogue: direct float2 stores
    const int r_base = m0 + warp_m * 32 + (lane >> 2);
    const int c_base = n0 + warp_n * 64 + (lane & 3) * 2;
    #pragma unroll
    for (int mi = 0; mi < 2; mi++) {
        #pragma unroll
        for (int ni = 0; ni < 8; ni++) {
            float* p0 = out + (size_t)(r_base + mi * 16) * NUM_STATE + c_base + ni * 8;
            float* p1 = out + (size_t)(r_base + mi * 16 + 8) * NUM_STATE + c_base + ni * 8;
            *reinterpret_cast<float2*>(p0) = make_float2(c[mi][ni][0], c[mi][ni][1]);
            *reinterpret_cast<float2*>(p1) = make_float2(c[mi][ni][2], c[mi][ni][3]);
        }
    }
}

// ---------------------------------------------------------------------------
// Launch
// ---------------------------------------------------------------------------
extern "C" void kernel_launch(void* const* d_in, const int* in_sizes, int n_in,
                              void* d_out, int out_size) {
    (void)in_sizes; (void)n_in; (void)out_size;
    // metadata order: state_embeddings(0, unused), alpha(1), context(2, unused), utm(3)
    const float* alpha = (const float*)d_in[1];
    const float* utm   = (const float*)d_in[3];
    float* out = (float*)d_out;

    cudaFuncSetAttribute(gemm_kernel, cudaFuncAttributeMaxDynamicSharedMemorySize, DYN_SMEM);

    row_stats_kernel<<<NUM_STATE, 256>>>(utm);
    build_matT_kernel<<<dim3(NUM_STATE / 32, NUM_STATE / 32), dim3(32, 8)>>>(utm);
    cvt_alpha_kernel<<<(BATCH * NUM_STATE) / (256 * 4), 256>>>(alpha);
    gemm_kernel<<<(BATCH / BM) * (NUM_STATE / BN), 256, DYN_SMEM>>>(out);
}

// round 4
// speedup vs baseline: 1.0134x; 1.0134x over previous
#include <cuda_runtime.h>
#include <cuda_bf16.h>
#include <cstdint>
#include <cstddef>

// Problem constants
#define NUM_STATE 2048
#define BATCH     4096

// ---------------------------------------------------------------------------
// Scratch (device globals; no cudaMalloc allowed)
// ---------------------------------------------------------------------------
__device__ __align__(16) __nv_bfloat16 g_alphaB[(size_t)BATCH * NUM_STATE];     // 16 MB
__device__ __align__(16) __nv_bfloat16 g_matT[(size_t)NUM_STATE * NUM_STATE];   // 8 MB, matT[t][s] = mat[s][t]
__device__ float g_rmax[NUM_STATE];
__device__ float g_rinv[NUM_STATE];

// ---------------------------------------------------------------------------
// Helpers
// ---------------------------------------------------------------------------
__device__ __forceinline__ uint32_t smem_u32(const void* p) {
    uint32_t a;
    asm("{ .reg .u64 t; cvta.to.shared.u64 t, %1; cvt.u32.u64 %0, t; }" : "=r"(a) : "l"(p));
    return a;
}

#define SWZ128(off) ((off) ^ (((off) >> 3) & 0x70))

__device__ __forceinline__ void cp_async16(uint32_t s, const void* g) {
    asm volatile("cp.async.cg.shared.global [%0], [%1], 16;" :: "r"(s), "l"(g) : "memory");
}
#define CP_COMMIT() asm volatile("cp.async.commit_group;" ::: "memory")
template <int N>
__device__ __forceinline__ void cp_wait() {
    asm volatile("cp.async.wait_group %0;" :: "n"(N) : "memory");
}

__device__ __forceinline__ void ldsm4(uint32_t* r, uint32_t addr) {
    asm volatile("ldmatrix.sync.aligned.m8n8.x4.shared.b16 {%0,%1,%2,%3}, [%4];"
                 : "=r"(r[0]), "=r"(r[1]), "=r"(r[2]), "=r"(r[3]) : "r"(addr));
}

__device__ __forceinline__ void mma_bf16(float* c, const uint32_t* a,
                                         uint32_t b0, uint32_t b1) {
    asm volatile(
        "mma.sync.aligned.m16n8k16.row.col.f32.bf16.bf16.f32 "
        "{%0,%1,%2,%3}, {%4,%5,%6,%7}, {%8,%9}, {%0,%1,%2,%3};"
        : "+f"(c[0]), "+f"(c[1]), "+f"(c[2]), "+f"(c[3])
        : "r"(a[0]), "r"(a[1]), "r"(a[2]), "r"(a[3]), "r"(b0), "r"(b1));
}

// ---------------------------------------------------------------------------
// Kernel 1: per-row softmax stats (max, 1/sum) over 2047 columns
// ---------------------------------------------------------------------------
__global__ void row_stats_kernel(const float* __restrict__ utm) {
    const int s = blockIdx.x;
    const float* row = utm + (size_t)s * (NUM_STATE - 1);
    const int tid = threadIdx.x;

    __shared__ float red[8];
    __shared__ float s_mx;

    float mx = -3.4e38f;
    for (int j = tid; j < NUM_STATE - 1; j += 256) mx = fmaxf(mx, row[j]);
    #pragma unroll
    for (int o = 16; o; o >>= 1) mx = fmaxf(mx, __shfl_xor_sync(0xffffffffu, mx, o));
    if ((tid & 31) == 0) red[tid >> 5] = mx;
    __syncthreads();
    if (tid == 0) {
        float m = red[0];
        #pragma unroll
        for (int i = 1; i < 8; i++) m = fmaxf(m, red[i]);
        s_mx = m;
    }
    __syncthreads();
    const float m = s_mx;

    float sm = 0.f;
    for (int j = tid; j < NUM_STATE - 1; j += 256) sm += __expf(row[j] - m);
    #pragma unroll
    for (int o = 16; o; o >>= 1) sm += __shfl_xor_sync(0xffffffffu, sm, o);
    if ((tid & 31) == 0) red[tid >> 5] = sm;
    __syncthreads();
    if (tid == 0) {
        float t = 0.f;
        #pragma unroll
        for (int i = 0; i < 8; i++) t += red[i];
        g_rmax[s] = m;
        g_rinv[s] = 1.0f / t;
    }
}

// ---------------------------------------------------------------------------
// Kernel 2: build matT[t][s] = mat[s][t] in bf16 (transposed so GEMM B operand
// is [N][K] row-major). mat[s][t] = (t==s) ? 0 : exp(u[s][t-(t>s)] - max[s]) * inv[s]
// ---------------------------------------------------------------------------
__global__ void build_matT_kernel(const float* __restrict__ utm) {
    const int s0 = blockIdx.x * 32;
    const int t0 = blockIdx.y * 32;
    const int tx = threadIdx.x;     // -> s
    const int ty = threadIdx.y;     // -> t (x4)
    const int tl = ty * 32 + tx;

    __shared__ float su[32][34];    // su[sy][cx] = u[s0+sy][t0-1+cx], cx in [0,33)

    for (int i = tl; i < 32 * 33; i += 256) {
        const int sy = i / 33;
        const int cx = i % 33;
        const int c = t0 - 1 + cx;
        su[sy][cx] = (c >= 0 && c < NUM_STATE - 1)
                       ? utm[(size_t)(s0 + sy) * (NUM_STATE - 1) + c] : 0.f;
    }
    __syncthreads();

    const int s = s0 + tx;
    const float mx = g_rmax[s];
    const float inv = g_rinv[s];

    #pragma unroll
    for (int k = 0; k < 4; k++) {
        const int yy = ty + 8 * k;
        const int t = t0 + yy;
        float v;
        if (t == s) {
            v = 0.f;
        } else {
            const int cx = yy + 1 - (t > s);   // = (t - (t>s)) - (t0-1)
            v = __expf(su[tx][cx] - mx) * inv;
        }
        g_matT[(size_t)t * NUM_STATE + s] = __float2bfloat16(v);
    }
}

// ---------------------------------------------------------------------------
// Kernel 3: alpha fp32 -> bf16
// ---------------------------------------------------------------------------
__global__ void cvt_alpha_kernel(const float* __restrict__ a) {
    const size_t i = ((size_t)blockIdx.x * blockDim.x + threadIdx.x) * 4;
    const float4 v = *reinterpret_cast<const float4*>(a + i);
    __nv_bfloat162 p0 = __floats2bfloat162_rn(v.x, v.y);
    __nv_bfloat162 p1 = __floats2bfloat162_rn(v.z, v.w);
    uint2 w;
    w.x = *reinterpret_cast<uint32_t*>(&p0);
    w.y = *reinterpret_cast<uint32_t*>(&p1);
    *reinterpret_cast<uint2*>(&g_alphaB[i]) = w;
}

// ---------------------------------------------------------------------------
// Kernel 4: mma.sync bf16 GEMM, C[4096,2048] = A[4096,2048] @ matT^T
//   A = g_alphaB  [M=4096][K=2048] row-major bf16
//   B = g_matT    [N=2048][K=2048] row-major bf16  (== col-major B for .row.col)
// CTA tile 128x128x64, 4-stage cp.async pipeline, 8 warps (4x2), warp 32x64.
// Register-level double buffering: ldmatrix for ks+1 issued before mma of ks.
// ---------------------------------------------------------------------------
static constexpr int BM = 128, BN = 128, BK = 64, STAGES = 4;
static constexpr int KITERS = NUM_STATE / BK;                       // 32
static constexpr int TILE_BYTES = BM * BK * 2;                      // 16384 (128B/row)
static constexpr int STAGE_BYTES = 2 * TILE_BYTES;                  // 32768
static constexpr int DYN_SMEM = STAGES * STAGE_BYTES + 1024;        // 132096

__global__ __launch_bounds__(256, 1) void gemm_kernel(float* __restrict__ out) {
    extern __shared__ char dsm[];
    const uint32_t dyn_base = (smem_u32(dsm) + 1023u) & ~1023u;

    const int tid = threadIdx.x;
    const int wid = tid >> 5;
    const int lane = tid & 31;

    const int tile = blockIdx.x;
    const int n0 = (tile & 15) * BN;
    const int m0 = (tile >> 4) * BM;

    const int warp_m = wid & 3;     // 4 slices of 32 rows
    const int warp_n = wid >> 2;    // 2 slices of 64 cols

    // ldmatrix x4 per-lane addressing: lanes 0-15 -> rows 0-15 of 16-row tile,
    // lanes 16-31 -> same rows, +16B (next 8 k-elems).
    const int lrow = lane & 15;
    const int lcol16 = (lane >> 4) & 1;

    auto load_stage = [&](int kit) {
        const int buf = kit & (STAGES - 1);
        const uint32_t sA = dyn_base + buf * STAGE_BYTES;
        const uint32_t sB = sA + TILE_BYTES;
        const int k0 = kit * BK;
        #pragma unroll
        for (int r = 0; r < 4; r++) {
            const int idx = tid + r * 256;       // 0..1023
            const int row = idx >> 3;
            const int c16 = idx & 7;
            const uint32_t soff = SWZ128((uint32_t)(row * 128 + c16 * 16));
            cp_async16(sA + soff, &g_alphaB[(size_t)(m0 + row) * NUM_STATE + k0 + c16 * 8]);
            cp_async16(sB + soff, &g_matT [(size_t)(n0 + row) * NUM_STATE + k0 + c16 * 8]);
        }
        CP_COMMIT();
    };

    float c[2][8][4];
    #pragma unroll
    for (int i = 0; i < 2; i++)
        #pragma unroll
        for (int j = 0; j < 8; j++)
            #pragma unroll
            for (int k = 0; k < 4; k++) c[i][j][k] = 0.f;

    // Double-buffered register fragments
    uint32_t af[2][2][4], bf[2][4][4];

    auto ldsm_ks = [&](uint32_t sA, uint32_t sB, int ks, int reg) {
        #pragma unroll
        for (int mi = 0; mi < 2; mi++) {
            const uint32_t off = (uint32_t)((warp_m * 32 + mi * 16 + lrow) * 128
                                            + ks * 32 + lcol16 * 16);
            ldsm4(af[reg][mi], sA + SWZ128(off));
        }
        #pragma unroll
        for (int nj = 0; nj < 4; nj++) {
            const uint32_t off = (uint32_t)((warp_n * 64 + nj * 16 + lrow) * 128
                                            + ks * 32 + lcol16 * 16);
            ldsm4(bf[reg][nj], sB + SWZ128(off));
        }
    };
    // ldmatrix x4 register layout:
    //   bf[r][nj][0] = (n 0-7 , k 0-7)   bf[r][nj][1] = (n 8-15, k 0-7)
    //   bf[r][nj][2] = (n 0-7 , k 8-15)  bf[r][nj][3] = (n 8-15, k 8-15)
    auto mma_ks = [&](int reg) {
        #pragma unroll
        for (int mi = 0; mi < 2; mi++)
            #pragma unroll
            for (int nj = 0; nj < 4; nj++) {
                mma_bf16(c[mi][nj * 2 + 0], af[reg][mi], bf[reg][nj][0], bf[reg][nj][2]);
                mma_bf16(c[mi][nj * 2 + 1], af[reg][mi], bf[reg][nj][1], bf[reg][nj][3]);
            }
    };

    // Prologue
    #pragma unroll
    for (int i = 0; i < STAGES - 1; i++) load_stage(i);

    for (int kit = 0; kit < KITERS; kit++) {
        const int buf = kit & (STAGES - 1);
        cp_wait<STAGES - 2>();
        __syncthreads();

        const uint32_t sA = dyn_base + buf * STAGE_BYTES;
        const uint32_t sB = sA + TILE_BYTES;

        // Prefetch ks=0 fragments, then issue next-stage cp.async so the LSU
        // burst overlaps tensor work instead of preceding it.
        ldsm_ks(sA, sB, 0, 0);
        if (kit + STAGES - 1 < KITERS) load_stage(kit + STAGES - 1);

        #pragma unroll
        for (int ks = 0; ks < BK / 16; ks++) {
            if (ks < BK / 16 - 1) ldsm_ks(sA, sB, ks + 1, (ks + 1) & 1);
            mma_ks(ks & 1);
        }
    }

    // Epilogue: direct float2 stores
    const int r_base = m0 + warp_m * 32 + (lane >> 2);
    const int c_base = n0 + warp_n * 64 + (lane & 3) * 2;
    #pragma unroll
    for (int mi = 0; mi < 2; mi++) {
        #pragma unroll
        for (int ni = 0; ni < 8; ni++) {
            float* p0 = out + (size_t)(r_base + mi * 16) * NUM_STATE + c_base + ni * 8;
            float* p1 = out + (size_t)(r_base + mi * 16 + 8) * NUM_STATE + c_base + ni * 8;
            *reinterpret_cast<float2*>(p0) = make_float2(c[mi][ni][0], c[mi][ni][1]);
            *reinterpret_cast<float2*>(p1) = make_float2(c[mi][ni][2], c[mi][ni][3]);
        }
    }
}

// ---------------------------------------------------------------------------
// Launch
// ---------------------------------------------------------------------------
extern "C" void kernel_launch(void* const* d_in, const int* in_sizes, int n_in,
                              void* d_out, int out_size) {
    (void)in_sizes; (void)n_in; (void)out_size;
    // metadata order: state_embeddings(0, unused), alpha(1), context(2, unused), utm(3)
    const float* alpha = (const float*)d_in[1];
    const float* utm   = (const float*)d_in[3];
    float* out = (float*)d_out;

    cudaFuncSetAttribute(gemm_kernel, cudaFuncAttributeMaxDynamicSharedMemorySize, DYN_SMEM);

    row_stats_kernel<<<NUM_STATE, 256>>>(utm);
    build_matT_kernel<<<dim3(NUM_STATE / 32, NUM_STATE / 32), dim3(32, 8)>>>(utm);
    cvt_alpha_kernel<<<(BATCH * NUM_STATE) / (256 * 4), 256>>>(alpha);
    gemm_kernel<<<(BATCH / BM) * (NUM_STATE / BN), 256, DYN_SMEM>>>(out);
}

// round 5
// speedup vs baseline: 1.0389x; 1.0251x over previous
#include <cuda_runtime.h>
#include <cuda_bf16.h>
#include <cstdint>
#include <cstddef>

// Problem constants
#define NUM_STATE 2048
#define BATCH     4096

// ---------------------------------------------------------------------------
// Scratch (device globals; no cudaMalloc allowed)
// ---------------------------------------------------------------------------
__device__ __align__(16) __nv_bfloat16 g_alphaB[(size_t)BATCH * NUM_STATE];     // 16 MB
__device__ __align__(16) __nv_bfloat16 g_matT[(size_t)NUM_STATE * NUM_STATE];   // 8 MB, matT[t][s] = mat[s][t]
__device__ float g_rmax[NUM_STATE];
__device__ float g_rinv[NUM_STATE];

// ---------------------------------------------------------------------------
// Helpers
// ---------------------------------------------------------------------------
__device__ __forceinline__ uint32_t smem_u32(const void* p) {
    uint32_t a;
    asm("{ .reg .u64 t; cvta.to.shared.u64 t, %1; cvt.u32.u64 %0, t; }" : "=r"(a) : "l"(p));
    return a;
}

#define SWZ128(off) ((off) ^ (((off) >> 3) & 0x70))

__device__ __forceinline__ void cp_async16(uint32_t s, const void* g) {
    asm volatile("cp.async.cg.shared.global [%0], [%1], 16;" :: "r"(s), "l"(g) : "memory");
}
#define CP_COMMIT() asm volatile("cp.async.commit_group;" ::: "memory")
template <int N>
__device__ __forceinline__ void cp_wait() {
    asm volatile("cp.async.wait_group %0;" :: "n"(N) : "memory");
}

__device__ __forceinline__ void ldsm4(uint32_t* r, uint32_t addr) {
    asm volatile("ldmatrix.sync.aligned.m8n8.x4.shared.b16 {%0,%1,%2,%3}, [%4];"
                 : "=r"(r[0]), "=r"(r[1]), "=r"(r[2]), "=r"(r[3]) : "r"(addr));
}

__device__ __forceinline__ void mma_bf16(float* c, const uint32_t* a,
                                         uint32_t b0, uint32_t b1) {
    asm volatile(
        "mma.sync.aligned.m16n8k16.row.col.f32.bf16.bf16.f32 "
        "{%0,%1,%2,%3}, {%4,%5,%6,%7}, {%8,%9}, {%0,%1,%2,%3};"
        : "+f"(c[0]), "+f"(c[1]), "+f"(c[2]), "+f"(c[3])
        : "r"(a[0]), "r"(a[1]), "r"(a[2]), "r"(a[3]), "r"(b0), "r"(b1));
}

// ---------------------------------------------------------------------------
// Kernel 1: per-row softmax stats, single pass over GMEM (row cached in smem)
// ---------------------------------------------------------------------------
__global__ void row_stats_kernel(const float* __restrict__ utm) {
    const int s = blockIdx.x;
    const float* row = utm + (size_t)s * (NUM_STATE - 1);
    const int tid = threadIdx.x;

    __shared__ float srow[NUM_STATE - 1];
    __shared__ float red[8];
    __shared__ float s_mx;

    float mx = -3.4e38f;
    for (int j = tid; j < NUM_STATE - 1; j += 256) {
        const float v = row[j];
        srow[j] = v;
        mx = fmaxf(mx, v);
    }
    #pragma unroll
    for (int o = 16; o; o >>= 1) mx = fmaxf(mx, __shfl_xor_sync(0xffffffffu, mx, o));
    if ((tid & 31) == 0) red[tid >> 5] = mx;
    __syncthreads();
    if (tid == 0) {
        float m = red[0];
        #pragma unroll
        for (int i = 1; i < 8; i++) m = fmaxf(m, red[i]);
        s_mx = m;
    }
    __syncthreads();
    const float m = s_mx;

    float sm = 0.f;
    for (int j = tid; j < NUM_STATE - 1; j += 256) sm += __expf(srow[j] - m);
    #pragma unroll
    for (int o = 16; o; o >>= 1) sm += __shfl_xor_sync(0xffffffffu, sm, o);
    if ((tid & 31) == 0) red[tid >> 5] = sm;
    __syncthreads();
    if (tid == 0) {
        float t = 0.f;
        #pragma unroll
        for (int i = 0; i < 8; i++) t += red[i];
        g_rmax[s] = m;
        g_rinv[s] = 1.0f / t;
    }
}

// ---------------------------------------------------------------------------
// Kernel 2: build matT[t][s] = mat[s][t] in bf16 (transposed so GEMM B operand
// is [N][K] row-major). mat[s][t] = (t==s) ? 0 : exp(u[s][t-(t>s)] - max[s]) * inv[s]
// ---------------------------------------------------------------------------
__global__ void build_matT_kernel(const float* __restrict__ utm) {
    const int s0 = blockIdx.x * 32;
    const int t0 = blockIdx.y * 32;
    const int tx = threadIdx.x;     // -> s
    const int ty = threadIdx.y;     // -> t (x4)
    const int tl = ty * 32 + tx;

    __shared__ float su[32][34];    // su[sy][cx] = u[s0+sy][t0-1+cx], cx in [0,33)

    for (int i = tl; i < 32 * 33; i += 256) {
        const int sy = i / 33;
        const int cx = i % 33;
        const int c = t0 - 1 + cx;
        su[sy][cx] = (c >= 0 && c < NUM_STATE - 1)
                       ? utm[(size_t)(s0 + sy) * (NUM_STATE - 1) + c] : 0.f;
    }
    __syncthreads();

    const int s = s0 + tx;
    const float mx = g_rmax[s];
    const float inv = g_rinv[s];

    #pragma unroll
    for (int k = 0; k < 4; k++) {
        const int yy = ty + 8 * k;
        const int t = t0 + yy;
        float v;
        if (t == s) {
            v = 0.f;
        } else {
            const int cx = yy + 1 - (t > s);   // = (t - (t>s)) - (t0-1)
            v = __expf(su[tx][cx] - mx) * inv;
        }
        g_matT[(size_t)t * NUM_STATE + s] = __float2bfloat16(v);
    }
}

// ---------------------------------------------------------------------------
// Kernel 3: alpha fp32 -> bf16
// ---------------------------------------------------------------------------
__global__ void cvt_alpha_kernel(const float* __restrict__ a) {
    const size_t i = ((size_t)blockIdx.x * blockDim.x + threadIdx.x) * 4;
    const float4 v = *reinterpret_cast<const float4*>(a + i);
    __nv_bfloat162 p0 = __floats2bfloat162_rn(v.x, v.y);
    __nv_bfloat162 p1 = __floats2bfloat162_rn(v.z, v.w);
    uint2 w;
    w.x = *reinterpret_cast<uint32_t*>(&p0);
    w.y = *reinterpret_cast<uint32_t*>(&p1);
    *reinterpret_cast<uint2*>(&g_alphaB[i]) = w;
}

// ---------------------------------------------------------------------------
// Kernel 4: mma.sync bf16 GEMM, C[4096,2048] = A[4096,2048] @ matT^T
//   A = g_alphaB  [M=4096][K=2048] row-major bf16
//   B = g_matT    [N=2048][K=2048] row-major bf16  (== col-major B for .row.col)
// CTA tile 128x128x64, 3-stage cp.async pipeline, 8 warps (4x2), warp 32x64.
// 2 CTAs / SM (regs capped at 128, 97KB smem) for cross-warp phase overlap.
// ---------------------------------------------------------------------------
static constexpr int BM = 128, BN = 128, BK = 64, STAGES = 3;
static constexpr int KITERS = NUM_STATE / BK;                       // 32
static constexpr int TILE_BYTES = BM * BK * 2;                      // 16384 (128B/row)
static constexpr int STAGE_BYTES = 2 * TILE_BYTES;                  // 32768
static constexpr int DYN_SMEM = STAGES * STAGE_BYTES + 1024;        // 99328

__global__ __launch_bounds__(256, 2) void gemm_kernel(float* __restrict__ out) {
    extern __shared__ char dsm[];
    const uint32_t dyn_base = (smem_u32(dsm) + 1023u) & ~1023u;

    const int tid = threadIdx.x;
    const int wid = tid >> 5;
    const int lane = tid & 31;

    const int tile = blockIdx.x;
    const int n0 = (tile & 15) * BN;
    const int m0 = (tile >> 4) * BM;

    const int warp_m = wid & 3;     // 4 slices of 32 rows
    const int warp_n = wid >> 2;    // 2 slices of 64 cols

    // ldmatrix x4 per-lane addressing: lanes 0-15 -> rows 0-15 of 16-row tile,
    // lanes 16-31 -> same rows, +16B (next 8 k-elems).
    const int lrow = lane & 15;
    const int lcol16 = (lane >> 4) & 1;

    // Precompute swizzled ldsm base offsets (tile-relative, ks=0).
    // SWZ128(base + ks*32) == SWZ128(base) ^ (ks*32): ks*32 only touches bits
    // 5-6 (disjoint from the lcol16 bit 4, no carry into row bits >=7), so the
    // per-ks address is a single XOR off the precomputed base.
    uint32_t aswz[2], bswz[4];
    #pragma unroll
    for (int mi = 0; mi < 2; mi++)
        aswz[mi] = SWZ128((uint32_t)((warp_m * 32 + mi * 16 + lrow) * 128 + lcol16 * 16));
    #pragma unroll
    for (int nj = 0; nj < 4; nj++)
        bswz[nj] = SWZ128((uint32_t)((warp_n * 64 + nj * 16 + lrow) * 128 + lcol16 * 16));

    auto load_stage = [&](int kit) {
        const int buf = kit % STAGES;
        const uint32_t sA = dyn_base + buf * STAGE_BYTES;
        const uint32_t sB = sA + TILE_BYTES;
        const int k0 = kit * BK;
        #pragma unroll
        for (int r = 0; r < 4; r++) {
            const int idx = tid + r * 256;       // 0..1023
            const int row = idx >> 3;
            const int c16 = idx & 7;
            const uint32_t soff = SWZ128((uint32_t)(row * 128 + c16 * 16));
            cp_async16(sA + soff, &g_alphaB[(size_t)(m0 + row) * NUM_STATE + k0 + c16 * 8]);
            cp_async16(sB + soff, &g_matT [(size_t)(n0 + row) * NUM_STATE + k0 + c16 * 8]);
        }
    };

    float c[2][8][4];
    #pragma unroll
    for (int i = 0; i < 2; i++)
        #pragma unroll
        for (int j = 0; j < 8; j++)
            #pragma unroll
            for (int k = 0; k < 4; k++) c[i][j][k] = 0.f;

    uint32_t af[2][4], bf[4][4];

    auto ldsm_ks = [&](uint32_t sA, uint32_t sB, int ks) {
        const uint32_t kx = (uint32_t)(ks << 5);
        #pragma unroll
        for (int mi = 0; mi < 2; mi++) ldsm4(af[mi], sA + (aswz[mi] ^ kx));
        #pragma unroll
        for (int nj = 0; nj < 4; nj++) ldsm4(bf[nj], sB + (bswz[nj] ^ kx));
    };
    // ldmatrix x4 register layout:
    //   bf[nj][0] = (n 0-7 , k 0-7)   bf[nj][1] = (n 8-15, k 0-7)
    //   bf[nj][2] = (n 0-7 , k 8-15)  bf[nj][3] = (n 8-15, k 8-15)
    auto mma_all = [&]() {
        #pragma unroll
        for (int mi = 0; mi < 2; mi++)
            #pragma unroll
            for (int nj = 0; nj < 4; nj++) {
                mma_bf16(c[mi][nj * 2 + 0], af[mi], bf[nj][0], bf[nj][2]);
                mma_bf16(c[mi][nj * 2 + 1], af[mi], bf[nj][1], bf[nj][3]);
            }
    };

    // Prologue: STAGES-1 groups in flight
    #pragma unroll
    for (int i = 0; i < STAGES - 1; i++) { load_stage(i); CP_COMMIT(); }

    for (int kit = 0; kit < KITERS; kit++) {
        const int buf = kit % STAGES;
        cp_wait<STAGES - 2>();   // exactly STAGES-1 groups pending -> stage kit done
        __syncthreads();

        const uint32_t sA = dyn_base + buf * STAGE_BYTES;
        const uint32_t sB = sA + TILE_BYTES;

        // Prefetch ks=0 fragments, then issue next-stage cp.async so the LSU
        // burst overlaps the ldsm latency + tensor work.
        ldsm_ks(sA, sB, 0);
        if (kit + STAGES - 1 < KITERS) load_stage(kit + STAGES - 1);
        CP_COMMIT();   // unconditional: keeps wait_group accounting exact in the tail

        #pragma unroll
        for (int ks = 0; ks < BK / 16; ks++) {
            mma_all();
            if (ks < BK / 16 - 1) ldsm_ks(sA, sB, ks + 1);
        }
    }

    // Epilogue: direct float2 stores
    const int r_base = m0 + warp_m * 32 + (lane >> 2);
    const int c_base = n0 + warp_n * 64 + (lane & 3) * 2;
    #pragma unroll
    for (int mi = 0; mi < 2; mi++) {
        #pragma unroll
        for (int ni = 0; ni < 8; ni++) {
            float* p0 = out + (size_t)(r_base + mi * 16) * NUM_STATE + c_base + ni * 8;
            float* p1 = out + (size_t)(r_base + mi * 16 + 8) * NUM_STATE + c_base + ni * 8;
            *reinterpret_cast<float2*>(p0) = make_float2(c[mi][ni][0], c[mi][ni][1]);
            *reinterpret_cast<float2*>(p1) = make_float2(c[mi][ni][2], c[mi][ni][3]);
        }
    }
}

// ---------------------------------------------------------------------------
// Launch
// ---------------------------------------------------------------------------
extern "C" void kernel_launch(void* const* d_in, const int* in_sizes, int n_in,
                              void* d_out, int out_size) {
    (void)in_sizes; (void)n_in; (void)out_size;
    // metadata order: state_embeddings(0, unused), alpha(1), context(2, unused), utm(3)
    const float* alpha = (const float*)d_in[1];
    const float* utm   = (const float*)d_in[3];
    float* out = (float*)d_out;

    cudaFuncSetAttribute(gemm_kernel, cudaFuncAttributeMaxDynamicSharedMemorySize, DYN_SMEM);

    row_stats_kernel<<<NUM_STATE, 256>>>(utm);
    build_matT_kernel<<<dim3(NUM_STATE / 32, NUM_STATE / 32), dim3(32, 8)>>>(utm);
    cvt_alpha_kernel<<<(BATCH * NUM_STATE) / (256 * 4), 256>>>(alpha);
    gemm_kernel<<<(BATCH / BM) * (NUM_STATE / BN), 256, DYN_SMEM>>>(out);
}

// round 6
// speedup vs baseline: 1.0792x; 1.0389x over previous
#include <cuda_runtime.h>
#include <cuda_bf16.h>
#include <cstdint>
#include <cstddef>

// Problem constants
#define NUM_STATE 2048
#define BATCH     4096

// ---------------------------------------------------------------------------
// Scratch (device globals; no cudaMalloc allowed)
// ---------------------------------------------------------------------------
__device__ __align__(16) __nv_bfloat16 g_alphaB[(size_t)BATCH * NUM_STATE];     // 16 MB
__device__ __align__(16) __nv_bfloat16 g_matT[(size_t)NUM_STATE * NUM_STATE];   // 8 MB, matT[t][s] = mat[s][t]
__device__ float g_rmax[NUM_STATE];
__device__ float g_rinv[NUM_STATE];

// ---------------------------------------------------------------------------
// Helpers
// ---------------------------------------------------------------------------
__device__ __forceinline__ uint32_t smem_u32(const void* p) {
    uint32_t a;
    asm("{ .reg .u64 t; cvta.to.shared.u64 t, %1; cvt.u32.u64 %0, t; }" : "=r"(a) : "l"(p));
    return a;
}

#define SWZ128(off) ((off) ^ (((off) >> 3) & 0x70))

__device__ __forceinline__ void cp_async16(uint32_t s, const void* g) {
    asm volatile("cp.async.cg.shared.global [%0], [%1], 16;" :: "r"(s), "l"(g) : "memory");
}
#define CP_COMMIT() asm volatile("cp.async.commit_group;" ::: "memory")
template <int N>
__device__ __forceinline__ void cp_wait() {
    asm volatile("cp.async.wait_group %0;" :: "n"(N) : "memory");
}

__device__ __forceinline__ void ldsm4(uint32_t* r, uint32_t addr) {
    asm volatile("ldmatrix.sync.aligned.m8n8.x4.shared.b16 {%0,%1,%2,%3}, [%4];"
                 : "=r"(r[0]), "=r"(r[1]), "=r"(r[2]), "=r"(r[3]) : "r"(addr));
}

__device__ __forceinline__ void mma_bf16(float* c, const uint32_t* a,
                                         uint32_t b0, uint32_t b1) {
    asm volatile(
        "mma.sync.aligned.m16n8k16.row.col.f32.bf16.bf16.f32 "
        "{%0,%1,%2,%3}, {%4,%5,%6,%7}, {%8,%9}, {%0,%1,%2,%3};"
        : "+f"(c[0]), "+f"(c[1]), "+f"(c[2]), "+f"(c[3])
        : "r"(a[0]), "r"(a[1]), "r"(a[2]), "r"(a[3]), "r"(b0), "r"(b1));
}

// ---------------------------------------------------------------------------
// Alpha fp32 -> bf16 conversion chunk (device helper; one block converts
// 1024 contiguous elements starting at cb*1024).
// ---------------------------------------------------------------------------
__device__ __forceinline__ void cvt_alpha_block(const float* __restrict__ a, int cb) {
    const size_t i = ((size_t)cb * 256 + threadIdx.x) * 4;
    const float4 v = *reinterpret_cast<const float4*>(a + i);
    __nv_bfloat162 p0 = __floats2bfloat162_rn(v.x, v.y);
    __nv_bfloat162 p1 = __floats2bfloat162_rn(v.z, v.w);
    uint2 w;
    w.x = *reinterpret_cast<uint32_t*>(&p0);
    w.y = *reinterpret_cast<uint32_t*>(&p1);
    *reinterpret_cast<uint2*>(&g_alphaB[i]) = w;
}

static constexpr int CVT_BLOCKS_TOTAL = (BATCH * NUM_STATE) / 1024;   // 8192
static constexpr int CVT1_BLOCKS = 4608;                              // with stats in K1
static constexpr int CVT2_BLOCKS = CVT_BLOCKS_TOTAL - CVT1_BLOCKS;    // 3584 with build in K2
static constexpr int STATS_BLOCKS = NUM_STATE;                        // 2048
static constexpr int BUILD_BLOCKS = (NUM_STATE / 32) * (NUM_STATE / 32); // 4096

// ---------------------------------------------------------------------------
// Kernel 1: [blocks 0..2047] per-row softmax stats (single GMEM pass, row in
// smem); [blocks 2048..] first slice of the alpha fp32->bf16 conversion.
// The two roles touch disjoint data and overlap on the machine.
// ---------------------------------------------------------------------------
__global__ __launch_bounds__(256) void prep1_kernel(const float* __restrict__ utm,
                                                    const float* __restrict__ alpha) {
    if (blockIdx.x >= STATS_BLOCKS) {
        cvt_alpha_block(alpha, blockIdx.x - STATS_BLOCKS);
        return;
    }
    const int s = blockIdx.x;
    const float* row = utm + (size_t)s * (NUM_STATE - 1);
    const int tid = threadIdx.x;

    __shared__ float srow[NUM_STATE - 1];
    __shared__ float red[8];
    __shared__ float s_mx;

    float mx = -3.4e38f;
    for (int j = tid; j < NUM_STATE - 1; j += 256) {
        const float v = row[j];
        srow[j] = v;
        mx = fmaxf(mx, v);
    }
    #pragma unroll
    for (int o = 16; o; o >>= 1) mx = fmaxf(mx, __shfl_xor_sync(0xffffffffu, mx, o));
    if ((tid & 31) == 0) red[tid >> 5] = mx;
    __syncthreads();
    if (tid == 0) {
        float m = red[0];
        #pragma unroll
        for (int i = 1; i < 8; i++) m = fmaxf(m, red[i]);
        s_mx = m;
    }
    __syncthreads();
    const float m = s_mx;

    float sm = 0.f;
    for (int j = tid; j < NUM_STATE - 1; j += 256) sm += __expf(srow[j] - m);
    #pragma unroll
    for (int o = 16; o; o >>= 1) sm += __shfl_xor_sync(0xffffffffu, sm, o);
    if ((tid & 31) == 0) red[tid >> 5] = sm;
    __syncthreads();
    if (tid == 0) {
        float t = 0.f;
        #pragma unroll
        for (int i = 0; i < 8; i++) t += red[i];
        g_rmax[s] = m;
        g_rinv[s] = 1.0f / t;
    }
}

// ---------------------------------------------------------------------------
// Kernel 2: [blocks 0..4095] build matT[t][s] = mat[s][t] in bf16 (needs the
// stats from kernel 1); [blocks 4096..] remaining alpha conversion slice.
// mat[s][t] = (t==s) ? 0 : exp(u[s][t-(t>s)] - max[s]) * inv[s]
// ---------------------------------------------------------------------------
__global__ __launch_bounds__(256) void prep2_kernel(const float* __restrict__ utm,
                                                    const float* __restrict__ alpha) {
    if (blockIdx.x >= BUILD_BLOCKS) {
        cvt_alpha_block(alpha, CVT1_BLOCKS + (int)blockIdx.x - BUILD_BLOCKS);
        return;
    }
    const int s0 = (blockIdx.x & 63) * 32;
    const int t0 = (blockIdx.x >> 6) * 32;
    const int tl = threadIdx.x;
    const int tx = tl & 31;        // -> s
    const int ty = tl >> 5;        // -> t (x4)

    __shared__ float su[32][34];   // su[sy][cx] = u[s0+sy][t0-1+cx], cx in [0,33)

    for (int i = tl; i < 32 * 33; i += 256) {
        const int sy = i / 33;
        const int cx = i % 33;
        const int c = t0 - 1 + cx;
        su[sy][cx] = (c >= 0 && c < NUM_STATE - 1)
                       ? utm[(size_t)(s0 + sy) * (NUM_STATE - 1) + c] : 0.f;
    }
    __syncthreads();

    const int s = s0 + tx;
    const float mx = g_rmax[s];
    const float inv = g_rinv[s];

    #pragma unroll
    for (int k = 0; k < 4; k++) {
        const int yy = ty + 8 * k;
        const int t = t0 + yy;
        float v;
        if (t == s) {
            v = 0.f;
        } else {
            const int cx = yy + 1 - (t > s);   // = (t - (t>s)) - (t0-1)
            v = __expf(su[tx][cx] - mx) * inv;
        }
        g_matT[(size_t)t * NUM_STATE + s] = __float2bfloat16(v);
    }
}

// ---------------------------------------------------------------------------
// Kernel 3: mma.sync bf16 GEMM, C[4096,2048] = A[4096,2048] @ matT^T
//   A = g_alphaB  [M=4096][K=2048] row-major bf16
//   B = g_matT    [N=2048][K=2048] row-major bf16  (== col-major B for .row.col)
// CTA tile 128x128x64, 3-stage cp.async pipeline, 8 warps (4x2), warp 32x64.
// 2 CTAs / SM (regs capped at 128, 97KB smem). Measured at the legacy-HMMA
// issue ceiling (~273 TF/s); scheduling changes are neutral (R4/R5 evidence).
// ---------------------------------------------------------------------------
static constexpr int BM = 128, BN = 128, BK = 64, STAGES = 3;
static constexpr int KITERS = NUM_STATE / BK;                       // 32
static constexpr int TILE_BYTES = BM * BK * 2;                      // 16384 (128B/row)
static constexpr int STAGE_BYTES = 2 * TILE_BYTES;                  // 32768
static constexpr int DYN_SMEM = STAGES * STAGE_BYTES + 1024;        // 99328

__global__ __launch_bounds__(256, 2) void gemm_kernel(float* __restrict__ out) {
    extern __shared__ char dsm[];
    const uint32_t dyn_base = (smem_u32(dsm) + 1023u) & ~1023u;

    const int tid = threadIdx.x;
    const int wid = tid >> 5;
    const int lane = tid & 31;

    const int tile = blockIdx.x;
    const int n0 = (tile & 15) * BN;
    const int m0 = (tile >> 4) * BM;

    const int warp_m = wid & 3;     // 4 slices of 32 rows
    const int warp_n = wid >> 2;    // 2 slices of 64 cols

    const int lrow = lane & 15;
    const int lcol16 = (lane >> 4) & 1;

    // Precomputed swizzled ldsm base offsets; per-ks address is base ^ (ks*32)
    // (ks*32 touches only bits 5-6, disjoint from swizzle-affected bits).
    uint32_t aswz[2], bswz[4];
    #pragma unroll
    for (int mi = 0; mi < 2; mi++)
        aswz[mi] = SWZ128((uint32_t)((warp_m * 32 + mi * 16 + lrow) * 128 + lcol16 * 16));
    #pragma unroll
    for (int nj = 0; nj < 4; nj++)
        bswz[nj] = SWZ128((uint32_t)((warp_n * 64 + nj * 16 + lrow) * 128 + lcol16 * 16));

    auto load_stage = [&](int kit) {
        const int buf = kit % STAGES;
        const uint32_t sA = dyn_base + buf * STAGE_BYTES;
        const uint32_t sB = sA + TILE_BYTES;
        const int k0 = kit * BK;
        #pragma unroll
        for (int r = 0; r < 4; r++) {
            const int idx = tid + r * 256;       // 0..1023
            const int row = idx >> 3;
            const int c16 = idx & 7;
            const uint32_t soff = SWZ128((uint32_t)(row * 128 + c16 * 16));
            cp_async16(sA + soff, &g_alphaB[(size_t)(m0 + row) * NUM_STATE + k0 + c16 * 8]);
            cp_async16(sB + soff, &g_matT [(size_t)(n0 + row) * NUM_STATE + k0 + c16 * 8]);
        }
    };

    float c[2][8][4];
    #pragma unroll
    for (int i = 0; i < 2; i++)
        #pragma unroll
        for (int j = 0; j < 8; j++)
            #pragma unroll
            for (int k = 0; k < 4; k++) c[i][j][k] = 0.f;

    uint32_t af[2][4], bf[4][4];

    auto ldsm_ks = [&](uint32_t sA, uint32_t sB, int ks) {
        const uint32_t kx = (uint32_t)(ks << 5);
        #pragma unroll
        for (int mi = 0; mi < 2; mi++) ldsm4(af[mi], sA + (aswz[mi] ^ kx));
        #pragma unroll
        for (int nj = 0; nj < 4; nj++) ldsm4(bf[nj], sB + (bswz[nj] ^ kx));
    };
    // ldmatrix x4 register layout:
    //   bf[nj][0] = (n 0-7 , k 0-7)   bf[nj][1] = (n 8-15, k 0-7)
    //   bf[nj][2] = (n 0-7 , k 8-15)  bf[nj][3] = (n 8-15, k 8-15)
    auto mma_all = [&]() {
        #pragma unroll
        for (int mi = 0; mi < 2; mi++)
            #pragma unroll
            for (int nj = 0; nj < 4; nj++) {
                mma_bf16(c[mi][nj * 2 + 0], af[mi], bf[nj][0], bf[nj][2]);
                mma_bf16(c[mi][nj * 2 + 1], af[mi], bf[nj][1], bf[nj][3]);
            }
    };

    // Prologue: STAGES-1 groups in flight
    #pragma unroll
    for (int i = 0; i < STAGES - 1; i++) { load_stage(i); CP_COMMIT(); }

    for (int kit = 0; kit < KITERS; kit++) {
        const int buf = kit % STAGES;
        cp_wait<STAGES - 2>();
        __syncthreads();

        const uint32_t sA = dyn_base + buf * STAGE_BYTES;
        const uint32_t sB = sA + TILE_BYTES;

        ldsm_ks(sA, sB, 0);
        if (kit + STAGES - 1 < KITERS) load_stage(kit + STAGES - 1);
        CP_COMMIT();   // unconditional: keeps wait_group accounting exact in the tail

        #pragma unroll
        for (int ks = 0; ks < BK / 16; ks++) {
            mma_all();
            if (ks < BK / 16 - 1) ldsm_ks(sA, sB, ks + 1);
        }
    }

    // Epilogue: direct float2 stores
    const int r_base = m0 + warp_m * 32 + (lane >> 2);
    const int c_base = n0 + warp_n * 64 + (lane & 3) * 2;
    #pragma unroll
    for (int mi = 0; mi < 2; mi++) {
        #pragma unroll
        for (int ni = 0; ni < 8; ni++) {
            float* p0 = out + (size_t)(r_base + mi * 16) * NUM_STATE + c_base + ni * 8;
            float* p1 = out + (size_t)(r_base + mi * 16 + 8) * NUM_STATE + c_base + ni * 8;
            *reinterpret_cast<float2*>(p0) = make_float2(c[mi][ni][0], c[mi][ni][1]);
            *reinterpret_cast<float2*>(p1) = make_float2(c[mi][ni][2], c[mi][ni][3]);
        }
    }
}

// ---------------------------------------------------------------------------
// Launch
// ---------------------------------------------------------------------------
extern "C" void kernel_launch(void* const* d_in, const int* in_sizes, int n_in,
                              void* d_out, int out_size) {
    (void)in_sizes; (void)n_in; (void)out_size;
    // metadata order: state_embeddings(0, unused), alpha(1), context(2, unused), utm(3)
    const float* alpha = (const float*)d_in[1];
    const float* utm   = (const float*)d_in[3];
    float* out = (float*)d_out;

    cudaFuncSetAttribute(gemm_kernel, cudaFuncAttributeMaxDynamicSharedMemorySize, DYN_SMEM);

    prep1_kernel<<<STATS_BLOCKS + CVT1_BLOCKS, 256>>>(utm, alpha);
    prep2_kernel<<<BUILD_BLOCKS + CVT2_BLOCKS, 256>>>(utm, alpha);
    gemm_kernel<<<(BATCH / BM) * (NUM_STATE / BN), 256, DYN_SMEM>>>(out);
}

// round 7
// speedup vs baseline: 1.1119x; 1.0302x over previous
#include <cuda_runtime.h>
#include <cuda_bf16.h>
#include <cstdint>
#include <cstddef>

// Problem constants
#define NUM_STATE 2048
#define BATCH     4096

// ---------------------------------------------------------------------------
// Scratch (device globals; no cudaMalloc allowed)
// ---------------------------------------------------------------------------
__device__ __align__(16) __nv_bfloat16 g_alphaB[(size_t)BATCH * NUM_STATE];     // 16 MB
__device__ __align__(16) __nv_bfloat16 g_matT[(size_t)NUM_STATE * NUM_STATE];   // 8 MB, matT[t][s] = mat[s][t]
__device__ float g_rmax[NUM_STATE];
__device__ float g_rinv[NUM_STATE];

// ---------------------------------------------------------------------------
// Helpers
// ---------------------------------------------------------------------------
__device__ __forceinline__ uint32_t smem_u32(const void* p) {
    uint32_t a;
    asm("{ .reg .u64 t; cvta.to.shared.u64 t, %1; cvt.u32.u64 %0, t; }" : "=r"(a) : "l"(p));
    return a;
}

#define SWZ128(off) ((off) ^ (((off) >> 3) & 0x70))

__device__ __forceinline__ void cp_async16(uint32_t s, const void* g) {
    asm volatile("cp.async.cg.shared.global [%0], [%1], 16;" :: "r"(s), "l"(g) : "memory");
}
#define CP_COMMIT() asm volatile("cp.async.commit_group;" ::: "memory")
template <int N>
__device__ __forceinline__ void cp_wait() {
    asm volatile("cp.async.wait_group %0;" :: "n"(N) : "memory");
}

__device__ __forceinline__ void ldsm4(uint32_t* r, uint32_t addr) {
    asm volatile("ldmatrix.sync.aligned.m8n8.x4.shared.b16 {%0,%1,%2,%3}, [%4];"
                 : "=r"(r[0]), "=r"(r[1]), "=r"(r[2]), "=r"(r[3]) : "r"(addr));
}

__device__ __forceinline__ void mma_bf16(float* c, const uint32_t* a,
                                         uint32_t b0, uint32_t b1) {
    asm volatile(
        "mma.sync.aligned.m16n8k16.row.col.f32.bf16.bf16.f32 "
        "{%0,%1,%2,%3}, {%4,%5,%6,%7}, {%8,%9}, {%0,%1,%2,%3};"
        : "+f"(c[0]), "+f"(c[1]), "+f"(c[2]), "+f"(c[3])
        : "r"(a[0]), "r"(a[1]), "r"(a[2]), "r"(a[3]), "r"(b0), "r"(b1));
}

// ---------------------------------------------------------------------------
// Alpha fp32 -> bf16 conversion chunk: one block converts 8192 contiguous
// elements (256 threads x 8 float4, all loads independent -> MLP 8).
// ---------------------------------------------------------------------------
static constexpr int CVT_CHUNK = 8192;
static constexpr int CVT_CHUNKS_TOTAL = (BATCH * NUM_STATE) / CVT_CHUNK;  // 1024
static constexpr int CVT1_CHUNKS = 576;                                    // in prep1
static constexpr int CVT2_CHUNKS = CVT_CHUNKS_TOTAL - CVT1_CHUNKS;         // 448 in prep2
static constexpr int STATS_BLOCKS = NUM_STATE;                             // 2048
static constexpr int BUILD_BLOCKS = (NUM_STATE / 32) * (NUM_STATE / 32);   // 4096

__device__ __forceinline__ void cvt_alpha_chunk(const float* __restrict__ a, int cb) {
    const size_t base = (size_t)cb * CVT_CHUNK + threadIdx.x * 4;
    float4 v[8];
    #pragma unroll
    for (int j = 0; j < 8; j++)
        v[j] = *reinterpret_cast<const float4*>(a + base + (size_t)j * 1024);
    #pragma unroll
    for (int j = 0; j < 8; j++) {
        __nv_bfloat162 p0 = __floats2bfloat162_rn(v[j].x, v[j].y);
        __nv_bfloat162 p1 = __floats2bfloat162_rn(v[j].z, v[j].w);
        uint2 w;
        w.x = *reinterpret_cast<uint32_t*>(&p0);
        w.y = *reinterpret_cast<uint32_t*>(&p1);
        *reinterpret_cast<uint2*>(&g_alphaB[base + (size_t)j * 1024]) = w;
    }
}

// ---------------------------------------------------------------------------
// Kernel 1: [blocks 0..2047] per-row softmax stats, register-resident row
// (8 elements/thread, MLP 8, no smem round-trip); [blocks 2048..] cvt chunks.
// ---------------------------------------------------------------------------
__global__ __launch_bounds__(256) void prep1_kernel(const float* __restrict__ utm,
                                                    const float* __restrict__ alpha) {
    if (blockIdx.x >= STATS_BLOCKS) {
        cvt_alpha_chunk(alpha, blockIdx.x - STATS_BLOCKS);
        return;
    }
    const int s = blockIdx.x;
    const float* row = utm + (size_t)s * (NUM_STATE - 1);
    const int tid = threadIdx.x;
    const int base = tid * 8;               // thread's 8 contiguous elements

    __shared__ float red[8];
    __shared__ float s_mx;

    // Load 8 elements into registers (independent LDG.32 -> MLP 8).
    // Rows are 4B-aligned only (2047*4 B stride), so scalar loads.
    float v[8];
    #pragma unroll
    for (int j = 0; j < 8; j++)
        v[j] = (base + j < NUM_STATE - 1) ? row[base + j] : -3.4e38f;

    float mx = v[0];
    #pragma unroll
    for (int j = 1; j < 8; j++) mx = fmaxf(mx, v[j]);
    #pragma unroll
    for (int o = 16; o; o >>= 1) mx = fmaxf(mx, __shfl_xor_sync(0xffffffffu, mx, o));
    if ((tid & 31) == 0) red[tid >> 5] = mx;
    __syncthreads();
    if (tid == 0) {
        float m = red[0];
        #pragma unroll
        for (int i = 1; i < 8; i++) m = fmaxf(m, red[i]);
        s_mx = m;
    }
    __syncthreads();
    const float m = s_mx;

    float sm = 0.f;
    #pragma unroll
    for (int j = 0; j < 8; j++)
        if (base + j < NUM_STATE - 1) sm += __expf(v[j] - m);
    #pragma unroll
    for (int o = 16; o; o >>= 1) sm += __shfl_xor_sync(0xffffffffu, sm, o);
    if ((tid & 31) == 0) red[tid >> 5] = sm;
    __syncthreads();
    if (tid == 0) {
        float t = 0.f;
        #pragma unroll
        for (int i = 0; i < 8; i++) t += red[i];
        g_rmax[s] = m;
        g_rinv[s] = 1.0f / t;
    }
}

// ---------------------------------------------------------------------------
// Kernel 2: [blocks 0..4095] build matT[t][s] = mat[s][t] in bf16 (needs the
// stats from kernel 1); [blocks 4096..] remaining cvt chunks.
// mat[s][t] = (t==s) ? 0 : exp(u[s][t-(t>s)] - max[s]) * inv[s]
// ---------------------------------------------------------------------------
__global__ __launch_bounds__(256) void prep2_kernel(const float* __restrict__ utm,
                                                    const float* __restrict__ alpha) {
    if (blockIdx.x >= BUILD_BLOCKS) {
        cvt_alpha_chunk(alpha, CVT1_CHUNKS + (int)blockIdx.x - BUILD_BLOCKS);
        return;
    }
    const int s0 = (blockIdx.x & 63) * 32;
    const int t0 = (blockIdx.x >> 6) * 32;
    const int tl = threadIdx.x;
    const int tx = tl & 31;        // -> s
    const int ty = tl >> 5;        // -> t (x4)

    __shared__ float su[32][34];   // su[sy][cx] = u[s0+sy][t0-1+cx], cx in [0,33)

    for (int i = tl; i < 32 * 33; i += 256) {
        const int sy = i / 33;
        const int cx = i % 33;
        const int c = t0 - 1 + cx;
        su[sy][cx] = (c >= 0 && c < NUM_STATE - 1)
                       ? utm[(size_t)(s0 + sy) * (NUM_STATE - 1) + c] : 0.f;
    }
    __syncthreads();

    const int s = s0 + tx;
    const float mx = g_rmax[s];
    const float inv = g_rinv[s];

    #pragma unroll
    for (int k = 0; k < 4; k++) {
        const int yy = ty + 8 * k;
        const int t = t0 + yy;
        float v;
        if (t == s) {
            v = 0.f;
        } else {
            const int cx = yy + 1 - (t > s);   // = (t - (t>s)) - (t0-1)
            v = __expf(su[tx][cx] - mx) * inv;
        }
        g_matT[(size_t)t * NUM_STATE + s] = __float2bfloat16(v);
    }
}

// ---------------------------------------------------------------------------
// Kernel 3: mma.sync bf16 GEMM, C[4096,2048] = A[4096,2048] @ matT^T
//   A = g_alphaB  [M=4096][K=2048] row-major bf16
//   B = g_matT    [N=2048][K=2048] row-major bf16  (== col-major B for .row.col)
// CTA tile 128x128x64, 3-stage cp.async pipeline, 8 warps (4x2), warp 32x64.
// 2 CTAs / SM (regs capped at 128, 97KB smem). Measured at the legacy-HMMA
// issue ceiling (~16 cyc/HMMA/SMSP -> ~120us floor); frozen since R5.
// ---------------------------------------------------------------------------
static constexpr int BM = 128, BN = 128, BK = 64, STAGES = 3;
static constexpr int KITERS = NUM_STATE / BK;                       // 32
static constexpr int TILE_BYTES = BM * BK * 2;                      // 16384 (128B/row)
static constexpr int STAGE_BYTES = 2 * TILE_BYTES;                  // 32768
static constexpr int DYN_SMEM = STAGES * STAGE_BYTES + 1024;        // 99328

__global__ __launch_bounds__(256, 2) void gemm_kernel(float* __restrict__ out) {
    extern __shared__ char dsm[];
    const uint32_t dyn_base = (smem_u32(dsm) + 1023u) & ~1023u;

    const int tid = threadIdx.x;
    const int wid = tid >> 5;
    const int lane = tid & 31;

    const int tile = blockIdx.x;
    const int n0 = (tile & 15) * BN;
    const int m0 = (tile >> 4) * BM;

    const int warp_m = wid & 3;     // 4 slices of 32 rows
    const int warp_n = wid >> 2;    // 2 slices of 64 cols

    const int lrow = lane & 15;
    const int lcol16 = (lane >> 4) & 1;

    // Precomputed swizzled ldsm base offsets; per-ks address is base ^ (ks*32)
    // (ks*32 touches only bits 5-6, disjoint from swizzle-affected bits).
    uint32_t aswz[2], bswz[4];
    #pragma unroll
    for (int mi = 0; mi < 2; mi++)
        aswz[mi] = SWZ128((uint32_t)((warp_m * 32 + mi * 16 + lrow) * 128 + lcol16 * 16));
    #pragma unroll
    for (int nj = 0; nj < 4; nj++)
        bswz[nj] = SWZ128((uint32_t)((warp_n * 64 + nj * 16 + lrow) * 128 + lcol16 * 16));

    auto load_stage = [&](int kit) {
        const int buf = kit % STAGES;
        const uint32_t sA = dyn_base + buf * STAGE_BYTES;
        const uint32_t sB = sA + TILE_BYTES;
        const int k0 = kit * BK;
        #pragma unroll
        for (int r = 0; r < 4; r++) {
            const int idx = tid + r * 256;       // 0..1023
            const int row = idx >> 3;
            const int c16 = idx & 7;
            const uint32_t soff = SWZ128((uint32_t)(row * 128 + c16 * 16));
            cp_async16(sA + soff, &g_alphaB[(size_t)(m0 + row) * NUM_STATE + k0 + c16 * 8]);
            cp_async16(sB + soff, &g_matT [(size_t)(n0 + row) * NUM_STATE + k0 + c16 * 8]);
        }
    };

    float c[2][8][4];
    #pragma unroll
    for (int i = 0; i < 2; i++)
        #pragma unroll
        for (int j = 0; j < 8; j++)
            #pragma unroll
            for (int k = 0; k < 4; k++) c[i][j][k] = 0.f;

    uint32_t af[2][4], bf[4][4];

    auto ldsm_ks = [&](uint32_t sA, uint32_t sB, int ks) {
        const uint32_t kx = (uint32_t)(ks << 5);
        #pragma unroll
        for (int mi = 0; mi < 2; mi++) ldsm4(af[mi], sA + (aswz[mi] ^ kx));
        #pragma unroll
        for (int nj = 0; nj < 4; nj++) ldsm4(bf[nj], sB + (bswz[nj] ^ kx));
    };
    // ldmatrix x4 register layout:
    //   bf[nj][0] = (n 0-7 , k 0-7)   bf[nj][1] = (n 8-15, k 0-7)
    //   bf[nj][2] = (n 0-7 , k 8-15)  bf[nj][3] = (n 8-15, k 8-15)
    auto mma_all = [&]() {
        #pragma unroll
        for (int mi = 0; mi < 2; mi++)
            #pragma unroll
            for (int nj = 0; nj < 4; nj++) {
                mma_bf16(c[mi][nj * 2 + 0], af[mi], bf[nj][0], bf[nj][2]);
                mma_bf16(c[mi][nj * 2 + 1], af[mi], bf[nj][1], bf[nj][3]);
            }
    };

    // Prologue: STAGES-1 groups in flight
    #pragma unroll
    for (int i = 0; i < STAGES - 1; i++) { load_stage(i); CP_COMMIT(); }

    for (int kit = 0; kit < KITERS; kit++) {
        const int buf = kit % STAGES;
        cp_wait<STAGES - 2>();
        __syncthreads();

        const uint32_t sA = dyn_base + buf * STAGE_BYTES;
        const uint32_t sB = sA + TILE_BYTES;

        ldsm_ks(sA, sB, 0);
        if (kit + STAGES - 1 < KITERS) load_stage(kit + STAGES - 1);
        CP_COMMIT();   // unconditional: keeps wait_group accounting exact in the tail

        #pragma unroll
        for (int ks = 0; ks < BK / 16; ks++) {
            mma_all();
            if (ks < BK / 16 - 1) ldsm_ks(sA, sB, ks + 1);
        }
    }

    // Epilogue: direct float2 stores
    const int r_base = m0 + warp_m * 32 + (lane >> 2);
    const int c_base = n0 + warp_n * 64 + (lane & 3) * 2;
    #pragma unroll
    for (int mi = 0; mi < 2; mi++) {
        #pragma unroll
        for (int ni = 0; ni < 8; ni++) {
            float* p0 = out + (size_t)(r_base + mi * 16) * NUM_STATE + c_base + ni * 8;
            float* p1 = out + (size_t)(r_base + mi * 16 + 8) * NUM_STATE + c_base + ni * 8;
            *reinterpret_cast<float2*>(p0) = make_float2(c[mi][ni][0], c[mi][ni][1]);
            *reinterpret_cast<float2*>(p1) = make_float2(c[mi][ni][2], c[mi][ni][3]);
        }
    }
}

// ---------------------------------------------------------------------------
// Launch
// ---------------------------------------------------------------------------
extern "C" void kernel_launch(void* const* d_in, const int* in_sizes, int n_in,
                              void* d_out, int out_size) {
    (void)in_sizes; (void)n_in; (void)out_size;
    // metadata order: state_embeddings(0, unused), alpha(1), context(2, unused), utm(3)
    const float* alpha = (const float*)d_in[1];
    const float* utm   = (const float*)d_in[3];
    float* out = (float*)d_out;

    cudaFuncSetAttribute(gemm_kernel, cudaFuncAttributeMaxDynamicSharedMemorySize, DYN_SMEM);

    prep1_kernel<<<STATS_BLOCKS + CVT1_CHUNKS, 256>>>(utm, alpha);
    prep2_kernel<<<BUILD_BLOCKS + CVT2_CHUNKS, 256>>>(utm, alpha);
    gemm_kernel<<<(BATCH / BM) * (NUM_STATE / BN), 256, DYN_SMEM>>>(out);
}